// round 5
// baseline (speedup 1.0000x reference)
#include <cuda_runtime.h>
#include <cuda_fp16.h>
#include <cstdint>

// MotilityModel via mma.sync fp16 (m16n8k16, fp32 accum) + 1024-thread CTAs.
//   h = cs @ W1^T + b1 ; h = LN(h)*gamma+beta ; relu ; out = h @ W2^T + b2
// N=500000, CS=64, H=256, S=3, fp32 in/out.

#define N_CELLS 500000
#define TILE_M  128
#define T_TILES ((N_CELLS + TILE_M - 1) / TILE_M)   // 3907
#define THREADS 1024                                 // 32 warps

#define AST 68   // A-tile row stride (floats)

// ---- smem layout (float offsets) ----
#define W1F_OFF 0
#define W1F_F   (8192)                   // 32KB fp16 fragment-major (2048 uint4)
#define AS_OFF  (W1F_OFF + W1F_F)
#define AS_F    (2 * 128 * AST)          // 17408 (2 buffers)
#define B1_OFF  (AS_OFF + AS_F)
#define GM_OFF  (B1_OFF + 256)
#define BE_OFF  (GM_OFF + 256)
#define W2_OFF  (BE_OFF + 256)           // [3][256]
#define B2_OFF  (W2_OFF + 768)
#define SR_OFF  (B2_OFF + 4)             // [4 ng][128 rows] float2 (s1,s2)
#define FR_OFF  (SR_OFF + 1024)          // [4 ng][384] float
#define SMEM_F  (FR_OFF + 1536)          // 29700 floats = 118800 B

typedef unsigned long long ull;

__device__ __forceinline__ void cp16(uint32_t dst, const void* src, int sz) {
    asm volatile("cp.async.cg.shared.global [%0], [%1], 16, %2;"
                 :: "r"(dst), "l"(src), "r"(sz) : "memory");
}
#define CP_COMMIT() asm volatile("cp.async.commit_group;" ::: "memory")
#define CP_WAIT1()  asm volatile("cp.async.wait_group 1;" ::: "memory")

__device__ __forceinline__ uint32_t h2(float lo, float hi) {
    __half2 h = __floats2half2_rn(lo, hi);          // lo -> bits[0:16]
    return *reinterpret_cast<uint32_t*>(&h);
}

// ---- packed f32x2 helpers (sm_100 family base ISA) ----
__device__ __forceinline__ ull pk2(float lo, float hi) {
    ull r; asm("mov.b64 %0, {%1, %2};" : "=l"(r) : "f"(lo), "f"(hi)); return r;
}
__device__ __forceinline__ void upk2(ull p, float& lo, float& hi) {
    asm("mov.b64 {%0, %1}, %2;" : "=f"(lo), "=f"(hi) : "l"(p));
}
__device__ __forceinline__ ull f2fma(ull a, ull b, ull c) {
    ull d; asm("fma.rn.f32x2 %0, %1, %2, %3;" : "=l"(d) : "l"(a), "l"(b), "l"(c)); return d;
}
__device__ __forceinline__ ull f2add(ull a, ull b) {
    ull d; asm("add.rn.f32x2 %0, %1, %2;" : "=l"(d) : "l"(a), "l"(b)); return d;
}
__device__ __forceinline__ ull f2mul(ull a, ull b) {
    ull d; asm("mul.rn.f32x2 %0, %1, %2;" : "=l"(d) : "l"(a), "l"(b)); return d;
}

#define MMA_F16(c, av, bv0, bv1) \
    asm volatile("mma.sync.aligned.m16n8k16.row.col.f32.f16.f16.f32 " \
        "{%0,%1,%2,%3}, {%4,%5,%6,%7}, {%8,%9}, {%0,%1,%2,%3};" \
        : "+f"((c)[0]), "+f"((c)[1]), "+f"((c)[2]), "+f"((c)[3]) \
        : "r"((av)[0]), "r"((av)[1]), "r"((av)[2]), "r"((av)[3]), \
          "r"(bv0), "r"(bv1))

__global__ void __launch_bounds__(THREADS, 1) motility_mma_kernel(
    const float* __restrict__ cs,   const float* __restrict__ W1,
    const float* __restrict__ b1,   const float* __restrict__ gamma,
    const float* __restrict__ beta, const float* __restrict__ W2,
    const float* __restrict__ b2,   float* __restrict__ out)
{
    extern __shared__ float sm[];
    float* W1f = sm + W1F_OFF;     // fp16 fragment-major (uint4 granularity)
    float* As  = sm + AS_OFF;
    float* b1s = sm + B1_OFF;
    float* gms = sm + GM_OFF;
    float* bes = sm + BE_OFF;
    float* w2s = sm + W2_OFF;
    float* b2s = sm + B2_OFF;
    float* sred = sm + SR_OFF;
    float* fred = sm + FR_OFF;

    const int tid  = threadIdx.x;
    const int lane = tid & 31;
    const int warp = tid >> 5;          // 0..31
    const int g    = lane >> 2;         // 0..7
    const int tg   = lane & 3;          // 0..3
    const int m_group = warp & 7;       // rows m_group*16..+15
    const int n_group = warp >> 3;      // cols n_group*64..+63
    const int bid  = blockIdx.x;
    const int GRID = gridDim.x;

    // ---- stage W1 as fp16 fragments (once; persistent kernel) ----
    // uint4 idx: lane | rg<<5 | ng<<7 | kk<<9 ; rg covers n-tiles {2rg, 2rg+1}
    // per n-tile: b0 = W1[col][k0..k0+1], b1 = W1[col][k0+8..k0+9], col = base+g
    #pragma unroll
    for (int i = 0; i < 2; i++) {
        int idx = tid + i * THREADS;            // 0..2047
        int li  = idx & 31;
        int rg  = (idx >> 5) & 3;
        int ng  = (idx >> 7) & 3;
        int kk  = idx >> 9;
        int gg = li >> 2, tt = li & 3;
        int k0 = kk * 16 + tt * 2;
        int ca = ng * 64 + (rg * 2) * 8 + gg;
        int cb = ca + 8;
        uint4 v;
        v.x = h2(W1[ca * 64 + k0],     W1[ca * 64 + k0 + 1]);
        v.y = h2(W1[ca * 64 + k0 + 8], W1[ca * 64 + k0 + 9]);
        v.z = h2(W1[cb * 64 + k0],     W1[cb * 64 + k0 + 1]);
        v.w = h2(W1[cb * 64 + k0 + 8], W1[cb * 64 + k0 + 9]);
        reinterpret_cast<uint4*>(W1f)[idx] = v;
    }
    if (tid < 256) { b1s[tid] = b1[tid]; gms[tid] = gamma[tid]; bes[tid] = beta[tid]; }
    if (tid < 768) w2s[tid] = W2[tid];
    if (tid < 3)   b2s[tid] = b2[tid];

    const int nT = (T_TILES - 1 - bid) / GRID + 1;
    const uint32_t as_base = (uint32_t)__cvta_generic_to_shared(As);

    auto loadA = [&](int j) {
        if (j < nT) {
            long tile = (long)bid + (long)j * GRID;
            const float* src = cs + tile * TILE_M * 64;
            uint32_t ab = as_base + (uint32_t)(j & 1) * (128 * AST * 4);
            long rowbase = tile * TILE_M;
            #pragma unroll
            for (int i = 0; i < 2; i++) {
                int idx = tid + i * THREADS;     // 0..2047 float4s
                int row = idx >> 4, c4 = idx & 15;
                int sz = (rowbase + row < N_CELLS) ? 16 : 0;
                cp16(ab + (uint32_t)(row * AST + c4 * 4) * 4, src + idx * 4, sz);
            }
        }
        CP_COMMIT();
    };

    loadA(0);

    const uint4* Bf = reinterpret_cast<const uint4*>(W1f) + n_group * 128 + lane;

    for (int j = 0; j < nT; j++) {
        loadA(j + 1);
        CP_WAIT1();
        __syncthreads();

        const long tile = (long)bid + (long)j * GRID;
        const float* Ab = As + (j & 1) * (128 * AST);

        // ---- acc init = b1 ----
        float acc[8][4];
        #pragma unroll
        for (int nt = 0; nt < 8; nt++) {
            int colp = n_group * 32 + nt * 4 + tg;
            float2 bv = reinterpret_cast<const float2*>(b1s)[colp];
            acc[nt][0] = bv.x; acc[nt][1] = bv.y;
            acc[nt][2] = bv.x; acc[nt][3] = bv.y;
        }

        // ---- GEMM1: 4 k16 steps; warp tile 16x64 ----
        const float* Ar0 = Ab + (m_group * 16 + g) * AST;
        const float* Ar8 = Ar0 + 8 * AST;
        #pragma unroll
        for (int kk = 0; kk < 4; kk++) {
            const int k0 = kk * 16 + tg * 2;
            float2 p00 = *reinterpret_cast<const float2*>(Ar0 + k0);
            float2 p80 = *reinterpret_cast<const float2*>(Ar8 + k0);
            float2 p08 = *reinterpret_cast<const float2*>(Ar0 + k0 + 8);
            float2 p88 = *reinterpret_cast<const float2*>(Ar8 + k0 + 8);
            uint32_t a[4];
            a[0] = h2(p00.x, p00.y);
            a[1] = h2(p80.x, p80.y);
            a[2] = h2(p08.x, p08.y);
            a[3] = h2(p88.x, p88.y);
            #pragma unroll
            for (int rg = 0; rg < 4; rg++) {
                uint4 bb = Bf[kk * 512 + rg * 32];
                MMA_F16(acc[rg * 2],     a, bb.x, bb.y);
                MMA_F16(acc[rg * 2 + 1], a, bb.z, bb.w);
            }
        }

        // ---- LN statistics (packed f32x2); h=0 row g, h=1 row g+8 ----
        ull s1p[2] = {0, 0}, s2p[2] = {0, 0};
        #pragma unroll
        for (int nt = 0; nt < 8; nt++)
            #pragma unroll
            for (int h = 0; h < 2; h++) {
                ull v = pk2(acc[nt][2 * h], acc[nt][2 * h + 1]);
                s1p[h] = f2add(s1p[h], v);
                s2p[h] = f2fma(v, v, s2p[h]);
            }
        float s1[2], s2[2];
        #pragma unroll
        for (int h = 0; h < 2; h++) {
            float lo, hi;
            upk2(s1p[h], lo, hi); s1[h] = lo + hi;
            upk2(s2p[h], lo, hi); s2[h] = lo + hi;
        }
        #pragma unroll
        for (int o = 1; o <= 2; o <<= 1)
            #pragma unroll
            for (int h = 0; h < 2; h++) {
                s1[h] += __shfl_xor_sync(0xffffffffu, s1[h], o);
                s2[h] += __shfl_xor_sync(0xffffffffu, s2[h], o);
            }
        if (tg == 0) {
            #pragma unroll
            for (int h = 0; h < 2; h++) {
                int row = m_group * 16 + g + 8 * h;
                reinterpret_cast<float2*>(sred)[n_group * 128 + row] =
                    make_float2(s1[h], s2[h]);
            }
        }
        __syncthreads();

        ull rs_p[2], nmu_p[2];
        #pragma unroll
        for (int h = 0; h < 2; h++) {
            int row = m_group * 16 + g + 8 * h;
            float t1 = 0.f, t2 = 0.f;
            #pragma unroll
            for (int ng = 0; ng < 4; ng++) {
                float2 v = reinterpret_cast<const float2*>(sred)[ng * 128 + row];
                t1 += v.x; t2 += v.y;
            }
            float m = t1 * (1.0f / 256.0f);
            float var = fmaf(-m, m, t2 * (1.0f / 256.0f));
            float rs = rsqrtf(var + 1e-5f);
            rs_p[h]  = pk2(rs, rs);
            nmu_p[h] = pk2(-m, -m);
        }

        // ---- normalize + affine + relu + project (packed f32x2) ----
        ull f0p[2] = {0, 0}, f1p[2] = {0, 0}, f2p[2] = {0, 0};
        #pragma unroll
        for (int nt = 0; nt < 8; nt++) {
            int colp = n_group * 32 + nt * 4 + tg;
            ull gv  = reinterpret_cast<const ull*>(gms)[colp];
            ull bev = reinterpret_cast<const ull*>(bes)[colp];
            ull w0  = reinterpret_cast<const ull*>(w2s)[colp];
            ull w1v = reinterpret_cast<const ull*>(w2s + 256)[colp];
            ull w2v = reinterpret_cast<const ull*>(w2s + 512)[colp];
            #pragma unroll
            for (int h = 0; h < 2; h++) {
                ull A = f2mul(rs_p[h], gv);
                ull B = f2fma(nmu_p[h], A, bev);
                ull vp = f2fma(pk2(acc[nt][2 * h], acc[nt][2 * h + 1]), A, B);
                float v0, v1;
                upk2(vp, v0, v1);
                v0 = fmaxf(v0, 0.0f); v1 = fmaxf(v1, 0.0f);
                ull vr = pk2(v0, v1);
                f0p[h] = f2fma(vr, w0,  f0p[h]);
                f1p[h] = f2fma(vr, w1v, f1p[h]);
                f2p[h] = f2fma(vr, w2v, f2p[h]);
            }
        }
        float f[2][3];
        #pragma unroll
        for (int h = 0; h < 2; h++) {
            float lo, hi;
            upk2(f0p[h], lo, hi); f[h][0] = lo + hi;
            upk2(f1p[h], lo, hi); f[h][1] = lo + hi;
            upk2(f2p[h], lo, hi); f[h][2] = lo + hi;
        }
        #pragma unroll
        for (int o = 1; o <= 2; o <<= 1)
            #pragma unroll
            for (int h = 0; h < 2; h++)
                #pragma unroll
                for (int s = 0; s < 3; s++)
                    f[h][s] += __shfl_xor_sync(0xffffffffu, f[h][s], o);
        if (tg == 0) {
            #pragma unroll
            for (int h = 0; h < 2; h++) {
                int row = m_group * 16 + g + 8 * h;
                #pragma unroll
                for (int s = 0; s < 3; s++)
                    fred[n_group * 384 + row * 3 + s] = f[h][s];
            }
        }
        __syncthreads();

        if (tid < 384) {
            long cell = tile * TILE_M + tid / 3;
            if (cell < N_CELLS) {
                float v = fred[tid] + fred[384 + tid] + fred[768 + tid]
                        + fred[1152 + tid] + b2s[tid - (tid / 3) * 3];
                out[tile * (TILE_M * 3) + tid] = v;
            }
        }
        __syncthreads();
    }
}

extern "C" void kernel_launch(void* const* d_in, const int* in_sizes, int n_in,
                              void* d_out, int out_size)
{
    const float* cs    = (const float*)d_in[0];
    const float* W1    = (const float*)d_in[1];
    const float* b1    = (const float*)d_in[2];
    const float* gamma = (const float*)d_in[3];
    const float* beta  = (const float*)d_in[4];
    const float* W2    = (const float*)d_in[5];
    const float* b2    = (const float*)d_in[6];
    float* out = (float*)d_out;

    int dev = 0, sms = 148;
    cudaGetDevice(&dev);
    cudaDeviceGetAttribute(&sms, cudaDevAttrMultiProcessorCount, dev);
    if (sms <= 0) sms = 148;
    int grid = sms < T_TILES ? sms : T_TILES;

    const size_t smem = SMEM_F * sizeof(float);   // 118800 B
    cudaFuncSetAttribute(motility_mma_kernel,
                         cudaFuncAttributeMaxDynamicSharedMemorySize, (int)smem);
    motility_mma_kernel<<<grid, THREADS, smem>>>(cs, W1, b1, gamma, beta, W2, b2, out);
}

// round 6
// speedup vs baseline: 1.2738x; 1.2738x over previous
#include <cuda_runtime.h>
#include <cuda_fp16.h>
#include <cstdint>

// MotilityModel via mma.sync fp16 (m16n8k16, fp32 accum), 512-thread CTAs,
// warp tile 32x64 (Round-4 shape), conflict-free A stride, fp16 B fragments.
//   h = cs @ W1^T + b1 ; h = LN(h)*gamma+beta ; relu ; out = h @ W2^T + b2
// N=500000, CS=64, H=256, S=3, fp32 in/out.

#define N_CELLS 500000
#define TILE_M  128
#define T_TILES ((N_CELLS + TILE_M - 1) / TILE_M)   // 3907
#define THREADS 512                                  // 16 warps

#define AST 72   // A row stride (floats): (8g+2tg) mod 32 distinct per phase

// ---- smem layout (float offsets) ----
#define W1F_OFF 0
#define W1F_F   8192                     // 32KB fp16 fragment-major (2048 uint4)
#define AS_OFF  (W1F_OFF + W1F_F)
#define AS_F    (2 * 128 * AST)          // 18432 (2 buffers)
#define B1_OFF  (AS_OFF + AS_F)
#define GM_OFF  (B1_OFF + 256)
#define BE_OFF  (GM_OFF + 256)
#define W2_OFF  (BE_OFF + 256)           // [3][256]
#define B2_OFF  (W2_OFF + 768)
#define SR_OFF  (B2_OFF + 4)             // [4 ng][128 rows] float2 (s1,s2)
#define FR_OFF  (SR_OFF + 1024)          // [4 ng][384] float
#define SMEM_F  (FR_OFF + 1536)          // 122,896 B

typedef unsigned long long ull;

__device__ __forceinline__ void cp16(uint32_t dst, const void* src, int sz) {
    asm volatile("cp.async.cg.shared.global [%0], [%1], 16, %2;"
                 :: "r"(dst), "l"(src), "r"(sz) : "memory");
}
#define CP_COMMIT() asm volatile("cp.async.commit_group;" ::: "memory")
#define CP_WAIT1()  asm volatile("cp.async.wait_group 1;" ::: "memory")

__device__ __forceinline__ uint32_t h2(float lo, float hi) {
    __half2 h = __floats2half2_rn(lo, hi);
    return *reinterpret_cast<uint32_t*>(&h);
}

// ---- packed f32x2 helpers ----
__device__ __forceinline__ ull pk2(float lo, float hi) {
    ull r; asm("mov.b64 %0, {%1, %2};" : "=l"(r) : "f"(lo), "f"(hi)); return r;
}
__device__ __forceinline__ void upk2(ull p, float& lo, float& hi) {
    asm("mov.b64 {%0, %1}, %2;" : "=f"(lo), "=f"(hi) : "l"(p));
}
__device__ __forceinline__ ull f2fma(ull a, ull b, ull c) {
    ull d; asm("fma.rn.f32x2 %0, %1, %2, %3;" : "=l"(d) : "l"(a), "l"(b), "l"(c)); return d;
}
__device__ __forceinline__ ull f2add(ull a, ull b) {
    ull d; asm("add.rn.f32x2 %0, %1, %2;" : "=l"(d) : "l"(a), "l"(b)); return d;
}
__device__ __forceinline__ ull f2mul(ull a, ull b) {
    ull d; asm("mul.rn.f32x2 %0, %1, %2;" : "=l"(d) : "l"(a), "l"(b)); return d;
}

#define MMA_F16(c, av, bv0, bv1) \
    asm volatile("mma.sync.aligned.m16n8k16.row.col.f32.f16.f16.f32 " \
        "{%0,%1,%2,%3}, {%4,%5,%6,%7}, {%8,%9}, {%0,%1,%2,%3};" \
        : "+f"((c)[0]), "+f"((c)[1]), "+f"((c)[2]), "+f"((c)[3]) \
        : "r"((av)[0]), "r"((av)[1]), "r"((av)[2]), "r"((av)[3]), \
          "r"(bv0), "r"(bv1))

__global__ void __launch_bounds__(THREADS, 1) motility_mma_kernel(
    const float* __restrict__ cs,   const float* __restrict__ W1,
    const float* __restrict__ b1,   const float* __restrict__ gamma,
    const float* __restrict__ beta, const float* __restrict__ W2,
    const float* __restrict__ b2,   float* __restrict__ out)
{
    extern __shared__ float sm[];
    float* W1f = sm + W1F_OFF;
    float* As  = sm + AS_OFF;
    float* b1s = sm + B1_OFF;
    float* gms = sm + GM_OFF;
    float* bes = sm + BE_OFF;
    float* w2s = sm + W2_OFF;
    float* b2s = sm + B2_OFF;
    float* sred = sm + SR_OFF;
    float* fred = sm + FR_OFF;

    const int tid  = threadIdx.x;
    const int lane = tid & 31;
    const int warp = tid >> 5;          // 0..15
    const int g    = lane >> 2;         // 0..7
    const int tg   = lane & 3;          // 0..3
    const int m_group = warp & 3;       // rows m_group*32..+31
    const int n_group = warp >> 2;      // cols n_group*64..+63
    const int bid  = blockIdx.x;
    const int GRID = gridDim.x;

    // ---- stage W1 as fp16 fragments (once; persistent kernel) ----
    // uint4 idx: lane | rg<<5 | ng<<7 | kk<<9 ; rg covers n-tiles {2rg,2rg+1}
    #pragma unroll
    for (int i = 0; i < 4; i++) {
        int idx = tid + i * THREADS;            // 0..2047
        int li  = idx & 31;
        int rg  = (idx >> 5) & 3;
        int ng  = (idx >> 7) & 3;
        int kk  = idx >> 9;
        int gg = li >> 2, tt = li & 3;
        int k0 = kk * 16 + tt * 2;
        int ca = ng * 64 + (rg * 2) * 8 + gg;
        int cb = ca + 8;
        uint4 v;
        v.x = h2(W1[ca * 64 + k0],     W1[ca * 64 + k0 + 1]);
        v.y = h2(W1[ca * 64 + k0 + 8], W1[ca * 64 + k0 + 9]);
        v.z = h2(W1[cb * 64 + k0],     W1[cb * 64 + k0 + 1]);
        v.w = h2(W1[cb * 64 + k0 + 8], W1[cb * 64 + k0 + 9]);
        reinterpret_cast<uint4*>(W1f)[idx] = v;
    }
    if (tid < 256) { b1s[tid] = b1[tid]; gms[tid] = gamma[tid]; bes[tid] = beta[tid]; }
    #pragma unroll
    for (int i = 0; i < 2; i++) {
        int idx = tid + i * THREADS;
        if (idx < 768) w2s[idx] = W2[idx];
    }
    if (tid < 3) b2s[tid] = b2[tid];

    const int nT = (T_TILES - 1 - bid) / GRID + 1;
    const uint32_t as_base = (uint32_t)__cvta_generic_to_shared(As);

    auto loadA = [&](int j) {
        if (j < nT) {
            long tile = (long)bid + (long)j * GRID;
            const float* src = cs + tile * TILE_M * 64;
            uint32_t ab = as_base + (uint32_t)(j & 1) * (128 * AST * 4);
            long rowbase = tile * TILE_M;
            #pragma unroll
            for (int i = 0; i < 4; i++) {
                int idx = tid + i * THREADS;     // 0..2047 float4s
                int row = idx >> 4, c4 = idx & 15;
                int sz = (rowbase + row < N_CELLS) ? 16 : 0;
                cp16(ab + (uint32_t)(row * AST + c4 * 4) * 4, src + idx * 4, sz);
            }
        }
        CP_COMMIT();
    };

    loadA(0);

    const uint4* Bf = reinterpret_cast<const uint4*>(W1f) + n_group * 128 + lane;

    for (int j = 0; j < nT; j++) {
        loadA(j + 1);
        CP_WAIT1();
        __syncthreads();

        const long tile = (long)bid + (long)j * GRID;
        const float* Ab = As + (j & 1) * (128 * AST);

        // ---- acc init = b1 ----
        float acc[2][8][4];
        #pragma unroll
        for (int nt = 0; nt < 8; nt++) {
            int colp = n_group * 32 + nt * 4 + tg;
            float2 bv = reinterpret_cast<const float2*>(b1s)[colp];
            #pragma unroll
            for (int mt = 0; mt < 2; mt++) {
                acc[mt][nt][0] = bv.x; acc[mt][nt][1] = bv.y;
                acc[mt][nt][2] = bv.x; acc[mt][nt][3] = bv.y;
            }
        }

        // ---- GEMM1: 4 k16 steps; warp tile 32x64 ----
        #pragma unroll
        for (int kk = 0; kk < 4; kk++) {
            const int k0 = kk * 16 + tg * 2;
            uint4 bb[4];
            #pragma unroll
            for (int rg = 0; rg < 4; rg++)
                bb[rg] = Bf[kk * 512 + rg * 32];

            uint32_t a[2][4];
            #pragma unroll
            for (int mt = 0; mt < 2; mt++) {
                const float* Ar0 = Ab + (m_group * 32 + mt * 16 + g) * AST;
                const float* Ar8 = Ar0 + 8 * AST;
                float2 p00 = *reinterpret_cast<const float2*>(Ar0 + k0);
                float2 p80 = *reinterpret_cast<const float2*>(Ar8 + k0);
                float2 p08 = *reinterpret_cast<const float2*>(Ar0 + k0 + 8);
                float2 p88 = *reinterpret_cast<const float2*>(Ar8 + k0 + 8);
                a[mt][0] = h2(p00.x, p00.y);
                a[mt][1] = h2(p80.x, p80.y);
                a[mt][2] = h2(p08.x, p08.y);
                a[mt][3] = h2(p88.x, p88.y);
            }
            #pragma unroll
            for (int mt = 0; mt < 2; mt++)
                #pragma unroll
                for (int rg = 0; rg < 4; rg++) {
                    MMA_F16(acc[mt][2 * rg],     a[mt], bb[rg].x, bb[rg].y);
                    MMA_F16(acc[mt][2 * rg + 1], a[mt], bb[rg].z, bb[rg].w);
                }
        }

        // ---- LN statistics (packed f32x2) ----
        ull s1p[2][2], s2p[2][2];
        #pragma unroll
        for (int mt = 0; mt < 2; mt++)
            #pragma unroll
            for (int h = 0; h < 2; h++) { s1p[mt][h] = 0ull; s2p[mt][h] = 0ull; }
        #pragma unroll
        for (int nt = 0; nt < 8; nt++)
            #pragma unroll
            for (int mt = 0; mt < 2; mt++)
                #pragma unroll
                for (int h = 0; h < 2; h++) {
                    ull v = pk2(acc[mt][nt][2 * h], acc[mt][nt][2 * h + 1]);
                    s1p[mt][h] = f2add(s1p[mt][h], v);
                    s2p[mt][h] = f2fma(v, v, s2p[mt][h]);
                }
        float s1[2][2], s2[2][2];
        #pragma unroll
        for (int mt = 0; mt < 2; mt++)
            #pragma unroll
            for (int h = 0; h < 2; h++) {
                float lo, hi;
                upk2(s1p[mt][h], lo, hi); s1[mt][h] = lo + hi;
                upk2(s2p[mt][h], lo, hi); s2[mt][h] = lo + hi;
            }
        #pragma unroll
        for (int o = 1; o <= 2; o <<= 1)
            #pragma unroll
            for (int mt = 0; mt < 2; mt++)
                #pragma unroll
                for (int h = 0; h < 2; h++) {
                    s1[mt][h] += __shfl_xor_sync(0xffffffffu, s1[mt][h], o);
                    s2[mt][h] += __shfl_xor_sync(0xffffffffu, s2[mt][h], o);
                }
        if (tg == 0) {
            #pragma unroll
            for (int mt = 0; mt < 2; mt++)
                #pragma unroll
                for (int h = 0; h < 2; h++) {
                    int row = m_group * 32 + mt * 16 + g + 8 * h;
                    reinterpret_cast<float2*>(sred)[n_group * 128 + row] =
                        make_float2(s1[mt][h], s2[mt][h]);
                }
        }
        __syncthreads();

        ull rs_p[2][2], nmu_p[2][2];
        #pragma unroll
        for (int mt = 0; mt < 2; mt++)
            #pragma unroll
            for (int h = 0; h < 2; h++) {
                int row = m_group * 32 + mt * 16 + g + 8 * h;
                float t1 = 0.f, t2 = 0.f;
                #pragma unroll
                for (int ng = 0; ng < 4; ng++) {
                    float2 v = reinterpret_cast<const float2*>(sred)[ng * 128 + row];
                    t1 += v.x; t2 += v.y;
                }
                float m = t1 * (1.0f / 256.0f);
                float var = fmaf(-m, m, t2 * (1.0f / 256.0f));
                float rs = rsqrtf(var + 1e-5f);
                rs_p[mt][h]  = pk2(rs, rs);
                nmu_p[mt][h] = pk2(-m, -m);
            }

        // ---- normalize + affine + relu + project (packed f32x2) ----
        ull f0p[2][2], f1p[2][2], f2p[2][2];
        #pragma unroll
        for (int mt = 0; mt < 2; mt++)
            #pragma unroll
            for (int h = 0; h < 2; h++) { f0p[mt][h] = 0; f1p[mt][h] = 0; f2p[mt][h] = 0; }

        #pragma unroll
        for (int nt = 0; nt < 8; nt++) {
            int colp = n_group * 32 + nt * 4 + tg;
            ull gv  = reinterpret_cast<const ull*>(gms)[colp];
            ull bev = reinterpret_cast<const ull*>(bes)[colp];
            ull w0  = reinterpret_cast<const ull*>(w2s)[colp];
            ull w1v = reinterpret_cast<const ull*>(w2s + 256)[colp];
            ull w2v = reinterpret_cast<const ull*>(w2s + 512)[colp];
            #pragma unroll
            for (int mt = 0; mt < 2; mt++)
                #pragma unroll
                for (int h = 0; h < 2; h++) {
                    ull A = f2mul(rs_p[mt][h], gv);
                    ull B = f2fma(nmu_p[mt][h], A, bev);
                    ull vp = f2fma(pk2(acc[mt][nt][2*h], acc[mt][nt][2*h + 1]), A, B);
                    float v0, v1;
                    upk2(vp, v0, v1);
                    v0 = fmaxf(v0, 0.0f); v1 = fmaxf(v1, 0.0f);
                    ull vr = pk2(v0, v1);
                    f0p[mt][h] = f2fma(vr, w0,  f0p[mt][h]);
                    f1p[mt][h] = f2fma(vr, w1v, f1p[mt][h]);
                    f2p[mt][h] = f2fma(vr, w2v, f2p[mt][h]);
                }
        }

        float f[2][2][3];
        #pragma unroll
        for (int mt = 0; mt < 2; mt++)
            #pragma unroll
            for (int h = 0; h < 2; h++) {
                float lo, hi;
                upk2(f0p[mt][h], lo, hi); f[mt][h][0] = lo + hi;
                upk2(f1p[mt][h], lo, hi); f[mt][h][1] = lo + hi;
                upk2(f2p[mt][h], lo, hi); f[mt][h][2] = lo + hi;
            }
        #pragma unroll
        for (int o = 1; o <= 2; o <<= 1)
            #pragma unroll
            for (int mt = 0; mt < 2; mt++)
                #pragma unroll
                for (int h = 0; h < 2; h++)
                    #pragma unroll
                    for (int s = 0; s < 3; s++)
                        f[mt][h][s] += __shfl_xor_sync(0xffffffffu, f[mt][h][s], o);
        if (tg == 0) {
            #pragma unroll
            for (int mt = 0; mt < 2; mt++)
                #pragma unroll
                for (int h = 0; h < 2; h++) {
                    int row = m_group * 32 + mt * 16 + g + 8 * h;
                    #pragma unroll
                    for (int s = 0; s < 3; s++)
                        fred[n_group * 384 + row * 3 + s] = f[mt][h][s];
                }
        }
        __syncthreads();

        if (tid < 384) {
            long cell = tile * TILE_M + tid / 3;
            if (cell < N_CELLS) {
                float v = fred[tid] + fred[384 + tid] + fred[768 + tid]
                        + fred[1152 + tid] + b2s[tid - (tid / 3) * 3];
                out[tile * (TILE_M * 3) + tid] = v;
            }
        }
        __syncthreads();
    }
}

extern "C" void kernel_launch(void* const* d_in, const int* in_sizes, int n_in,
                              void* d_out, int out_size)
{
    const float* cs    = (const float*)d_in[0];
    const float* W1    = (const float*)d_in[1];
    const float* b1    = (const float*)d_in[2];
    const float* gamma = (const float*)d_in[3];
    const float* beta  = (const float*)d_in[4];
    const float* W2    = (const float*)d_in[5];
    const float* b2    = (const float*)d_in[6];
    float* out = (float*)d_out;

    int dev = 0, sms = 148;
    cudaGetDevice(&dev);
    cudaDeviceGetAttribute(&sms, cudaDevAttrMultiProcessorCount, dev);
    if (sms <= 0) sms = 148;
    int grid = sms < T_TILES ? sms : T_TILES;

    const size_t smem = SMEM_F * sizeof(float);   // 122,896 B
    cudaFuncSetAttribute(motility_mma_kernel,
                         cudaFuncAttributeMaxDynamicSharedMemorySize, (int)smem);
    motility_mma_kernel<<<grid, THREADS, smem>>>(cs, W1, b1, gamma, beta, W2, b2, out);
}

// round 7
// speedup vs baseline: 1.3393x; 1.0514x over previous
#include <cuda_runtime.h>
#include <cuda_fp16.h>
#include <cstdint>

// MotilityModel via mma.sync fp16 (m16n8k16, fp32 accum).
// 256-thread CTAs, 2 CTAs/SM co-resident (independent barrier domains),
// block tile 64x256, warp tile 32x64, conflict-free A stride.
//   h = cs @ W1^T + b1 ; h = LN(h)*gamma+beta ; relu ; out = h @ W2^T + b2
// N=500000, CS=64, H=256, S=3, fp32 in/out.

#define N_CELLS 500000
#define TILE_M  64
#define T_TILES ((N_CELLS + TILE_M - 1) / TILE_M)   // 7813
#define THREADS 256                                  // 8 warps

#define AST 72   // A row stride (floats): (8g+2tg) mod 32 distinct per phase

// ---- smem layout (float offsets) ----
#define W1F_OFF 0
#define W1F_F   8192                     // 32KB fp16 fragment-major (2048 uint4)
#define AS_OFF  (W1F_OFF + W1F_F)
#define AS_F    (2 * TILE_M * AST)       // 9216 (2 buffers)
#define B1_OFF  (AS_OFF + AS_F)
#define GM_OFF  (B1_OFF + 256)
#define BE_OFF  (GM_OFF + 256)
#define W2_OFF  (BE_OFF + 256)           // [3][256]
#define B2_OFF  (W2_OFF + 768)
#define SR_OFF  (B2_OFF + 4)             // [4 ng][64 rows] float2 (s1,s2)
#define FR_OFF  (SR_OFF + 512)           // [4 ng][192] float
#define SMEM_F  (FR_OFF + 768)           // 20228 floats = 80912 B

typedef unsigned long long ull;

__device__ __forceinline__ void cp16(uint32_t dst, const void* src, int sz) {
    asm volatile("cp.async.cg.shared.global [%0], [%1], 16, %2;"
                 :: "r"(dst), "l"(src), "r"(sz) : "memory");
}
#define CP_COMMIT() asm volatile("cp.async.commit_group;" ::: "memory")
#define CP_WAIT1()  asm volatile("cp.async.wait_group 1;" ::: "memory")

__device__ __forceinline__ uint32_t h2(float lo, float hi) {
    __half2 h = __floats2half2_rn(lo, hi);
    return *reinterpret_cast<uint32_t*>(&h);
}

// ---- packed f32x2 helpers ----
__device__ __forceinline__ ull pk2(float lo, float hi) {
    ull r; asm("mov.b64 %0, {%1, %2};" : "=l"(r) : "f"(lo), "f"(hi)); return r;
}
__device__ __forceinline__ void upk2(ull p, float& lo, float& hi) {
    asm("mov.b64 {%0, %1}, %2;" : "=f"(lo), "=f"(hi) : "l"(p));
}
__device__ __forceinline__ ull f2fma(ull a, ull b, ull c) {
    ull d; asm("fma.rn.f32x2 %0, %1, %2, %3;" : "=l"(d) : "l"(a), "l"(b), "l"(c)); return d;
}
__device__ __forceinline__ ull f2add(ull a, ull b) {
    ull d; asm("add.rn.f32x2 %0, %1, %2;" : "=l"(d) : "l"(a), "l"(b)); return d;
}
__device__ __forceinline__ ull f2mul(ull a, ull b) {
    ull d; asm("mul.rn.f32x2 %0, %1, %2;" : "=l"(d) : "l"(a), "l"(b)); return d;
}

#define MMA_F16(c, av, bv0, bv1) \
    asm volatile("mma.sync.aligned.m16n8k16.row.col.f32.f16.f16.f32 " \
        "{%0,%1,%2,%3}, {%4,%5,%6,%7}, {%8,%9}, {%0,%1,%2,%3};" \
        : "+f"((c)[0]), "+f"((c)[1]), "+f"((c)[2]), "+f"((c)[3]) \
        : "r"((av)[0]), "r"((av)[1]), "r"((av)[2]), "r"((av)[3]), \
          "r"(bv0), "r"(bv1))

__global__ void __launch_bounds__(THREADS, 2) motility_mma_kernel(
    const float* __restrict__ cs,   const float* __restrict__ W1,
    const float* __restrict__ b1,   const float* __restrict__ gamma,
    const float* __restrict__ beta, const float* __restrict__ W2,
    const float* __restrict__ b2,   float* __restrict__ out)
{
    extern __shared__ float sm[];
    float* W1f = sm + W1F_OFF;
    float* As  = sm + AS_OFF;
    float* b1s = sm + B1_OFF;
    float* gms = sm + GM_OFF;
    float* bes = sm + BE_OFF;
    float* w2s = sm + W2_OFF;
    float* b2s = sm + B2_OFF;
    float* sred = sm + SR_OFF;
    float* fred = sm + FR_OFF;

    const int tid  = threadIdx.x;
    const int lane = tid & 31;
    const int warp = tid >> 5;          // 0..7
    const int g    = lane >> 2;         // 0..7
    const int tg   = lane & 3;          // 0..3
    const int m_group = warp & 1;       // rows m_group*32..+31
    const int n_group = warp >> 1;      // cols n_group*64..+63
    const int bid  = blockIdx.x;
    const int GRID = gridDim.x;

    // ---- stage W1 as fp16 fragments (once; persistent kernel) ----
    // uint4 idx: lane | rg<<5 | ng<<7 | kk<<9 ; rg covers n-tiles {2rg,2rg+1}
    #pragma unroll
    for (int i = 0; i < 8; i++) {
        int idx = tid + i * THREADS;            // 0..2047
        int li  = idx & 31;
        int rg  = (idx >> 5) & 3;
        int ng  = (idx >> 7) & 3;
        int kk  = idx >> 9;
        int gg = li >> 2, tt = li & 3;
        int k0 = kk * 16 + tt * 2;
        int ca = ng * 64 + (rg * 2) * 8 + gg;
        int cb = ca + 8;
        uint4 v;
        v.x = h2(W1[ca * 64 + k0],     W1[ca * 64 + k0 + 1]);
        v.y = h2(W1[ca * 64 + k0 + 8], W1[ca * 64 + k0 + 9]);
        v.z = h2(W1[cb * 64 + k0],     W1[cb * 64 + k0 + 1]);
        v.w = h2(W1[cb * 64 + k0 + 8], W1[cb * 64 + k0 + 9]);
        reinterpret_cast<uint4*>(W1f)[idx] = v;
    }
    if (tid < 256) { b1s[tid] = b1[tid]; gms[tid] = gamma[tid]; bes[tid] = beta[tid]; }
    #pragma unroll
    for (int i = 0; i < 3; i++) {
        int idx = tid + i * THREADS;
        if (idx < 768) w2s[idx] = W2[idx];
    }
    if (tid < 3) b2s[tid] = b2[tid];

    const int nT = (T_TILES - 1 - bid) / GRID + 1;
    const uint32_t as_base = (uint32_t)__cvta_generic_to_shared(As);

    auto loadA = [&](int j) {
        if (j < nT) {
            long tile = (long)bid + (long)j * GRID;
            const float* src = cs + tile * TILE_M * 64;
            uint32_t ab = as_base + (uint32_t)(j & 1) * (TILE_M * AST * 4);
            long rowbase = tile * TILE_M;
            #pragma unroll
            for (int i = 0; i < 4; i++) {
                int idx = tid + i * THREADS;     // 0..1023 float4s
                int row = idx >> 4, c4 = idx & 15;
                int sz = (rowbase + row < N_CELLS) ? 16 : 0;
                cp16(ab + (uint32_t)(row * AST + c4 * 4) * 4, src + idx * 4, sz);
            }
        }
        CP_COMMIT();
    };

    loadA(0);

    const uint4* Bf = reinterpret_cast<const uint4*>(W1f) + n_group * 128 + lane;

    for (int j = 0; j < nT; j++) {
        loadA(j + 1);
        CP_WAIT1();
        __syncthreads();

        const long tile = (long)bid + (long)j * GRID;
        const float* Ab = As + (j & 1) * (TILE_M * AST);

        // ---- acc init = b1 ----
        float acc[2][8][4];
        #pragma unroll
        for (int nt = 0; nt < 8; nt++) {
            int colp = n_group * 32 + nt * 4 + tg;
            float2 bv = reinterpret_cast<const float2*>(b1s)[colp];
            #pragma unroll
            for (int mt = 0; mt < 2; mt++) {
                acc[mt][nt][0] = bv.x; acc[mt][nt][1] = bv.y;
                acc[mt][nt][2] = bv.x; acc[mt][nt][3] = bv.y;
            }
        }

        // ---- GEMM1: 4 k16 steps; warp tile 32x64 ----
        #pragma unroll
        for (int kk = 0; kk < 4; kk++) {
            const int k0 = kk * 16 + tg * 2;
            uint4 bb[4];
            #pragma unroll
            for (int rg = 0; rg < 4; rg++)
                bb[rg] = Bf[kk * 512 + rg * 32];

            uint32_t a[2][4];
            #pragma unroll
            for (int mt = 0; mt < 2; mt++) {
                const float* Ar0 = Ab + (m_group * 32 + mt * 16 + g) * AST;
                const float* Ar8 = Ar0 + 8 * AST;
                float2 p00 = *reinterpret_cast<const float2*>(Ar0 + k0);
                float2 p80 = *reinterpret_cast<const float2*>(Ar8 + k0);
                float2 p08 = *reinterpret_cast<const float2*>(Ar0 + k0 + 8);
                float2 p88 = *reinterpret_cast<const float2*>(Ar8 + k0 + 8);
                a[mt][0] = h2(p00.x, p00.y);
                a[mt][1] = h2(p80.x, p80.y);
                a[mt][2] = h2(p08.x, p08.y);
                a[mt][3] = h2(p88.x, p88.y);
            }
            #pragma unroll
            for (int mt = 0; mt < 2; mt++)
                #pragma unroll
                for (int rg = 0; rg < 4; rg++) {
                    MMA_F16(acc[mt][2 * rg],     a[mt], bb[rg].x, bb[rg].y);
                    MMA_F16(acc[mt][2 * rg + 1], a[mt], bb[rg].z, bb[rg].w);
                }
        }

        // ---- LN statistics (packed f32x2) ----
        ull s1p[2][2], s2p[2][2];
        #pragma unroll
        for (int mt = 0; mt < 2; mt++)
            #pragma unroll
            for (int h = 0; h < 2; h++) { s1p[mt][h] = 0ull; s2p[mt][h] = 0ull; }
        #pragma unroll
        for (int nt = 0; nt < 8; nt++)
            #pragma unroll
            for (int mt = 0; mt < 2; mt++)
                #pragma unroll
                for (int h = 0; h < 2; h++) {
                    ull v = pk2(acc[mt][nt][2 * h], acc[mt][nt][2 * h + 1]);
                    s1p[mt][h] = f2add(s1p[mt][h], v);
                    s2p[mt][h] = f2fma(v, v, s2p[mt][h]);
                }
        float s1[2][2], s2[2][2];
        #pragma unroll
        for (int mt = 0; mt < 2; mt++)
            #pragma unroll
            for (int h = 0; h < 2; h++) {
                float lo, hi;
                upk2(s1p[mt][h], lo, hi); s1[mt][h] = lo + hi;
                upk2(s2p[mt][h], lo, hi); s2[mt][h] = lo + hi;
            }
        #pragma unroll
        for (int o = 1; o <= 2; o <<= 1)
            #pragma unroll
            for (int mt = 0; mt < 2; mt++)
                #pragma unroll
                for (int h = 0; h < 2; h++) {
                    s1[mt][h] += __shfl_xor_sync(0xffffffffu, s1[mt][h], o);
                    s2[mt][h] += __shfl_xor_sync(0xffffffffu, s2[mt][h], o);
                }
        if (tg == 0) {
            #pragma unroll
            for (int mt = 0; mt < 2; mt++)
                #pragma unroll
                for (int h = 0; h < 2; h++) {
                    int row = m_group * 32 + mt * 16 + g + 8 * h;
                    reinterpret_cast<float2*>(sred)[n_group * 64 + row] =
                        make_float2(s1[mt][h], s2[mt][h]);
                }
        }
        __syncthreads();

        ull rs_p[2][2], nmu_p[2][2];
        #pragma unroll
        for (int mt = 0; mt < 2; mt++)
            #pragma unroll
            for (int h = 0; h < 2; h++) {
                int row = m_group * 32 + mt * 16 + g + 8 * h;
                float t1 = 0.f, t2 = 0.f;
                #pragma unroll
                for (int ng = 0; ng < 4; ng++) {
                    float2 v = reinterpret_cast<const float2*>(sred)[ng * 64 + row];
                    t1 += v.x; t2 += v.y;
                }
                float m = t1 * (1.0f / 256.0f);
                float var = fmaf(-m, m, t2 * (1.0f / 256.0f));
                float rs = rsqrtf(var + 1e-5f);
                rs_p[mt][h]  = pk2(rs, rs);
                nmu_p[mt][h] = pk2(-m, -m);
            }

        // ---- normalize + affine + relu + project (packed f32x2) ----
        ull f0p[2][2], f1p[2][2], f2p[2][2];
        #pragma unroll
        for (int mt = 0; mt < 2; mt++)
            #pragma unroll
            for (int h = 0; h < 2; h++) { f0p[mt][h] = 0; f1p[mt][h] = 0; f2p[mt][h] = 0; }

        #pragma unroll
        for (int nt = 0; nt < 8; nt++) {
            int colp = n_group * 32 + nt * 4 + tg;
            ull gv  = reinterpret_cast<const ull*>(gms)[colp];
            ull bev = reinterpret_cast<const ull*>(bes)[colp];
            ull w0  = reinterpret_cast<const ull*>(w2s)[colp];
            ull w1v = reinterpret_cast<const ull*>(w2s + 256)[colp];
            ull w2v = reinterpret_cast<const ull*>(w2s + 512)[colp];
            #pragma unroll
            for (int mt = 0; mt < 2; mt++)
                #pragma unroll
                for (int h = 0; h < 2; h++) {
                    ull A = f2mul(rs_p[mt][h], gv);
                    ull B = f2fma(nmu_p[mt][h], A, bev);
                    ull vp = f2fma(pk2(acc[mt][nt][2*h], acc[mt][nt][2*h + 1]), A, B);
                    float v0, v1;
                    upk2(vp, v0, v1);
                    v0 = fmaxf(v0, 0.0f); v1 = fmaxf(v1, 0.0f);
                    ull vr = pk2(v0, v1);
                    f0p[mt][h] = f2fma(vr, w0,  f0p[mt][h]);
                    f1p[mt][h] = f2fma(vr, w1v, f1p[mt][h]);
                    f2p[mt][h] = f2fma(vr, w2v, f2p[mt][h]);
                }
        }

        float f[2][2][3];
        #pragma unroll
        for (int mt = 0; mt < 2; mt++)
            #pragma unroll
            for (int h = 0; h < 2; h++) {
                float lo, hi;
                upk2(f0p[mt][h], lo, hi); f[mt][h][0] = lo + hi;
                upk2(f1p[mt][h], lo, hi); f[mt][h][1] = lo + hi;
                upk2(f2p[mt][h], lo, hi); f[mt][h][2] = lo + hi;
            }
        #pragma unroll
        for (int o = 1; o <= 2; o <<= 1)
            #pragma unroll
            for (int mt = 0; mt < 2; mt++)
                #pragma unroll
                for (int h = 0; h < 2; h++)
                    #pragma unroll
                    for (int s = 0; s < 3; s++)
                        f[mt][h][s] += __shfl_xor_sync(0xffffffffu, f[mt][h][s], o);
        if (tg == 0) {
            #pragma unroll
            for (int mt = 0; mt < 2; mt++)
                #pragma unroll
                for (int h = 0; h < 2; h++) {
                    int row = m_group * 32 + mt * 16 + g + 8 * h;
                    #pragma unroll
                    for (int s = 0; s < 3; s++)
                        fred[n_group * 192 + row * 3 + s] = f[mt][h][s];
                }
        }
        __syncthreads();

        if (tid < 192) {
            long cell = tile * TILE_M + tid / 3;
            if (cell < N_CELLS) {
                float v = fred[tid] + fred[192 + tid] + fred[384 + tid]
                        + fred[576 + tid] + b2s[tid - (tid / 3) * 3];
                out[tile * (TILE_M * 3) + tid] = v;
            }
        }
        __syncthreads();
    }
}

extern "C" void kernel_launch(void* const* d_in, const int* in_sizes, int n_in,
                              void* d_out, int out_size)
{
    const float* cs    = (const float*)d_in[0];
    const float* W1    = (const float*)d_in[1];
    const float* b1    = (const float*)d_in[2];
    const float* gamma = (const float*)d_in[3];
    const float* beta  = (const float*)d_in[4];
    const float* W2    = (const float*)d_in[5];
    const float* b2    = (const float*)d_in[6];
    float* out = (float*)d_out;

    int dev = 0, sms = 148;
    cudaGetDevice(&dev);
    cudaDeviceGetAttribute(&sms, cudaDevAttrMultiProcessorCount, dev);
    if (sms <= 0) sms = 148;
    int grid = 2 * sms;
    if (grid > T_TILES) grid = T_TILES;

    const size_t smem = SMEM_F * sizeof(float);   // 80912 B
    cudaFuncSetAttribute(motility_mma_kernel,
                         cudaFuncAttributeMaxDynamicSharedMemorySize, (int)smem);
    motility_mma_kernel<<<grid, THREADS, smem>>>(cs, W1, b1, gamma, beta, W2, b2, out);
}